// round 2
// baseline (speedup 1.0000x reference)
#include <cuda_runtime.h>
#include <cstdint>
#include <cstddef>

#define TDIM 512
#define BDIM 128
#define EDIM 128
#define SDIM 1024
#define INFV 3.0e38f

// ---------------- device scratch (no allocation allowed) ----------------
__device__ float g_LTB[TDIM * BDIM];   // [t][b] post-pop level L_t
__device__ float g_t0TB[TDIM * BDIM];  // [t][b] C_init of slot 2t  (= L_{t-1}+d1)
__device__ float g_TPTB[TDIM * BDIM];  // [t][b] C_init of slot 2t+1 (= pre-pop total)
__device__ float g_cTB[TDIM * BDIM];   // [t][b] u - TP
__device__ float g_mT[SDIM * TDIM];    // [j][t] m value (max over batch)

// ---------------- K1: per-batch level recurrence (sequential in t) -------
__global__ void k_levels(const float* __restrict__ d1,
                         const float* __restrict__ d2,
                         const float* __restrict__ u) {
    int b = threadIdx.x;  // 128 threads, 1 block
    float L = 0.f;
#pragma unroll 4
    for (int t = 0; t < TDIM; ++t) {
        float a1 = d1[t * BDIM + b];
        float a2 = d2[t * BDIM + b];
        float uu = u[t * BDIM + b];
        float top0 = L + a1;
        float TP = top0 + a2;
        g_t0TB[t * BDIM + b] = top0;
        g_TPTB[t * BDIM + b] = TP;
        g_cTB[t * BDIM + b] = uu - TP;
        L = fmaxf(0.f, TP - uu);
        g_LTB[t * BDIM + b] = L;
    }
}

// ---------------- K2: m[t][j] = max_b (c[b,t] + C_j(b,t)) ----------------
// One CTA handles 4 consecutive t values; 128 threads = one per batch.
__global__ __launch_bounds__(128) void k_m() {
    int t0 = blockIdx.x * 4;
    int b = threadIdx.x;
    int lane = b & 31, wrp = b >> 5;
    __shared__ float red[4][8];

    float c0 = g_cTB[(t0 + 0) * BDIM + b];
    float c1 = g_cTB[(t0 + 1) * BDIM + b];
    float c2 = g_cTB[(t0 + 2) * BDIM + b];
    float c3 = g_cTB[(t0 + 3) * BDIM + b];
    float S0 = INFV, S1 = INFV, S2 = INFV, S3 = INFV;

    for (int tau = t0 + 3; tau >= 0; --tau) {
        float Lv = g_LTB[tau * BDIM + b];
        float t0v = g_t0TB[tau * BDIM + b];
        float tpv = g_TPTB[tau * BDIM + b];
        float x[8];

#define DO_I(i, Si, ci)                                           \
        {                                                         \
            int ti = t0 + (i);                                    \
            if (tau <= ti) {                                      \
                float suf = (tau < ti) ? fminf(Si, Lv) : INFV;    \
                x[2 * (i) + 0] = (ci) + fminf(t0v, suf);          \
                x[2 * (i) + 1] = (ci) + fminf(tpv, suf);          \
                Si = suf;                                         \
            } else {                                              \
                x[2 * (i) + 0] = -INFV;                           \
                x[2 * (i) + 1] = -INFV;                           \
            }                                                     \
        }
        DO_I(0, S0, c0)
        DO_I(1, S1, c1)
        DO_I(2, S2, c2)
        DO_I(3, S3, c3)
#undef DO_I

#pragma unroll
        for (int k = 0; k < 8; ++k) {
            float v = x[k];
#pragma unroll
            for (int o = 16; o; o >>= 1)
                v = fmaxf(v, __shfl_xor_sync(0xffffffffu, v, o));
            if (lane == 0) red[wrp][k] = v;
        }
        __syncthreads();
        if (b < 8) {
            float v = fmaxf(fmaxf(red[0][b], red[1][b]),
                            fmaxf(red[2][b], red[3][b]));
            int i = b >> 1, e = b & 1;
            int ti = t0 + i;
            if (tau <= ti)
                g_mT[(size_t)(2 * tau + e) * TDIM + ti] = v;
        }
        __syncthreads();
    }
}

// ---------------- K3: triangular weighted GEMM ---------------------------
// out[t,b,:] = sum_{tau<=t} w(t,2tau)*v1[tau,b,:] + w(t,2tau+1)*v2[tau,b,:]
// CTA = (64-row t tile) x (one batch b). 256 threads: 4 rows x 8 cols each.
__global__ __launch_bounds__(256) void k_gemm(const float* __restrict__ v1,
                                              const float* __restrict__ v2,
                                              float* __restrict__ out) {
    int t0 = blockIdx.x * 64;
    int b = blockIdx.y;
    int tid = threadIdx.x;
    int rg = tid >> 4;        // 0..15 -> rows t0+rg*4 .. +3
    int ex = tid & 15;        // 0..15 -> cols ex*8 .. +7
    int r0 = t0 + rg * 4;
    int e0 = ex * 8;

    __shared__ float sv1[2][EDIM];
    __shared__ float sv2[2][EDIM];
    __shared__ float sm0[2][64];
    __shared__ float sm1[2][64];
    __shared__ float ssc[2][4];

    float acc[4][8];
#pragma unroll
    for (int i = 0; i < 4; ++i)
#pragma unroll
        for (int c = 0; c < 8; ++c) acc[i][c] = 0.f;

    float runmin[4] = {INFV, INFV, INFV, INFV};
    float prevA[4] = {0.f, 0.f, 0.f, 0.f};

    auto stage = [&](int tau, int buf) {
        if (tid < 128) {
            int t1 = tau + 1;
            sv1[buf][tid] =
                (t1 < TDIM) ? v1[((size_t)t1 * BDIM + b) * EDIM + tid] : 0.f;
        } else {
            sv2[buf][tid - 128] = v2[((size_t)tau * BDIM + b) * EDIM + (tid - 128)];
        }
        if (tid < 64) {
            sm1[buf][tid] = g_mT[(size_t)(2 * tau + 1) * TDIM + t0 + tid];
        } else if (tid < 128) {
            int j = 2 * tau + 2;
            sm0[buf][tid - 64] =
                (j < SDIM) ? g_mT[(size_t)j * TDIM + t0 + (tid - 64)] : 0.f;
        } else if (tid == 128) {
            ssc[buf][0] = g_LTB[tau * BDIM + b];
        } else if (tid == 129) {
            ssc[buf][1] = g_t0TB[tau * BDIM + b];
        } else if (tid == 130) {
            ssc[buf][2] = g_TPTB[tau * BDIM + b];
        }
    };

    int taumax = t0 + 63;
    stage(taumax, 0);

    for (int tau = taumax; tau >= 0; --tau) {
        int buf = (taumax - tau) & 1;
        __syncthreads();
        if (tau > 0) stage(tau - 1, buf ^ 1);

        float Lv = ssc[buf][0];
        float t0v = ssc[buf][1];
        float tpv = ssc[buf][2];

        float w0[4], w1[4];
#pragma unroll
        for (int i = 0; i < 4; ++i) {
            int tr = r0 + i;
            float suf = (tau < tr) ? fminf(runmin[i], Lv) : INFV;
            float Av = fminf(t0v, suf);
            float Bv = fminf(tpv, suf);
            // slot 2*tau+1 (pushed v2[tau]): strength = Bv - Av
            w1[i] = (tau <= tr) ? fminf(Bv - Av, sm1[buf][rg * 4 + i]) : 0.f;
            // deferred slot 2*(tau+1) (pushed v1[tau+1]): strength = A_{tau+1} - Bv
            w0[i] = (tau + 1 <= tr) ? fminf(prevA[i] - Bv, sm0[buf][rg * 4 + i]) : 0.f;
            runmin[i] = suf;
            prevA[i] = Av;
        }
#pragma unroll
        for (int c = 0; c < 8; ++c) {
            float a = sv1[buf][e0 + c];
            float p = sv2[buf][e0 + c];
#pragma unroll
            for (int i = 0; i < 4; ++i) acc[i][c] += w1[i] * p + w0[i] * a;
        }
    }

    // epilogue: slot 0 -> weight min(C_0, m[t][0]) times v1[0,b,:]
    __syncthreads();
    if (tid < 128) {
        sv1[0][tid] = v1[(size_t)b * EDIM + tid];  // t=0 row
    } else if (tid < 192) {
        sm0[0][tid - 128] = g_mT[(size_t)0 * TDIM + t0 + (tid - 128)];
    }
    __syncthreads();

    float w0f[4];
#pragma unroll
    for (int i = 0; i < 4; ++i) w0f[i] = fminf(prevA[i], sm0[0][rg * 4 + i]);
#pragma unroll
    for (int c = 0; c < 8; ++c) {
        float a = sv1[0][e0 + c];
#pragma unroll
        for (int i = 0; i < 4; ++i) acc[i][c] += w0f[i] * a;
    }

    // write out [T][B][E]
#pragma unroll
    for (int i = 0; i < 4; ++i) {
        size_t base = ((size_t)(r0 + i) * BDIM + b) * EDIM + e0;
        float4 lo = make_float4(acc[i][0], acc[i][1], acc[i][2], acc[i][3]);
        float4 hi = make_float4(acc[i][4], acc[i][5], acc[i][6], acc[i][7]);
        *reinterpret_cast<float4*>(out + base) = lo;
        *reinterpret_cast<float4*>(out + base + 4) = hi;
    }
}

extern "C" void kernel_launch(void* const* d_in, const int* in_sizes, int n_in,
                              void* d_out, int out_size) {
    const float* v1 = (const float*)d_in[0];
    const float* v2 = (const float*)d_in[1];
    const float* d1 = (const float*)d_in[2];
    const float* d2 = (const float*)d_in[3];
    const float* u  = (const float*)d_in[4];
    float* out = (float*)d_out;

    k_levels<<<1, BDIM>>>(d1, d2, u);
    k_m<<<TDIM / 4, BDIM>>>();
    dim3 grid(TDIM / 64, BDIM);
    k_gemm<<<grid, 256>>>(v1, v2, out);
}

// round 3
// speedup vs baseline: 2.6115x; 2.6115x over previous
#include <cuda_runtime.h>
#include <cstdint>
#include <cstddef>

#define TDIM 512
#define BDIM 128
#define EDIM 128
#define SDIM 1024
#define NLEV 10
#define PBSTRIDE (NLEV * TDIM)
#define INFV 3.0e38f

// ---------------- device scratch ----------------
__device__ float g_cTB[TDIM * BDIM];       // [t][b] u - TP
__device__ float g_t0T[BDIM * TDIM];       // [b][tau] Cinit of slot 2tau
__device__ float g_TPT[BDIM * TDIM];       // [b][tau] Cinit of slot 2tau+1
__device__ float g_P[BDIM * PBSTRIDE];     // [b][k][tau] sparse min table (k=0 is L)
__device__ float g_m[SDIM * TDIM];         // [j][t]
__device__ float g_A[8 * BDIM];
__device__ float g_B[8 * BDIM];
__device__ float g_Ls[8 * BDIM];

// ---------------- packed f32x2 helpers ----------------
__device__ __forceinline__ unsigned long long ffma2(unsigned long long a,
                                                    unsigned long long b,
                                                    unsigned long long c) {
    unsigned long long d;
    asm("fma.rn.f32x2 %0, %1, %2, %3;" : "=l"(d) : "l"(a), "l"(b), "l"(c));
    return d;
}
__device__ __forceinline__ unsigned long long pack2(float x) {
    unsigned long long d;
    asm("mov.b64 %0, {%1, %2};" : "=l"(d) : "f"(x), "f"(x));
    return d;
}
__device__ __forceinline__ void unpack2(unsigned long long v, float& lo, float& hi) {
    asm("mov.b64 {%0, %1}, %2;" : "=f"(lo), "=f"(hi) : "l"(v));
}

// ---------------- K1a: per-chunk scan composition (A, B) -----------------
__global__ void k_lev1(const float* __restrict__ d1, const float* __restrict__ d2,
                       const float* __restrict__ u) {
    int c = blockIdx.x, b = threadIdx.x;
    float A = 0.f, Bv = 0.f;
    int t0 = c * 64;
#pragma unroll 4
    for (int t = t0; t < t0 + 64; ++t) {
        float x = d1[t * BDIM + b] + d2[t * BDIM + b] - u[t * BDIM + b];
        A += x;
        Bv = fmaxf(Bv + x, 0.f);
    }
    g_A[c * BDIM + b] = A;
    g_B[c * BDIM + b] = Bv;
}

// ---------------- K1b: compose chunk states ------------------------------
__global__ void k_lev2() {
    int b = threadIdx.x;
    float L = 0.f;
#pragma unroll
    for (int c = 0; c < 8; ++c) {
        g_Ls[c * BDIM + b] = L;
        L = fmaxf(L + g_A[c * BDIM + b], g_B[c * BDIM + b]);
    }
}

// ---------------- K1c: recompute chunk with known start; emit arrays -----
__global__ void k_lev3(const float* __restrict__ d1, const float* __restrict__ d2,
                       const float* __restrict__ u) {
    int c = blockIdx.x, b = threadIdx.x;
    float L = g_Ls[c * BDIM + b];
    int t0 = c * 64;
#pragma unroll 4
    for (int t = t0; t < t0 + 64; ++t) {
        float a1 = d1[t * BDIM + b];
        float a2 = d2[t * BDIM + b];
        float uu = u[t * BDIM + b];
        float top0 = L + a1;
        float TP = top0 + a2;
        g_t0T[b * TDIM + t] = top0;
        g_TPT[b * TDIM + t] = TP;
        g_cTB[t * BDIM + b] = uu - TP;
        L = fmaxf(TP - uu, 0.f);
        g_P[b * PBSTRIDE + t] = L;  // level 0
    }
}

// ---------------- K2: sparse table levels 1..9 ---------------------------
__global__ __launch_bounds__(256) void k_table() {
    int b = blockIdx.x, tid = threadIdx.x;
    __shared__ float s0[TDIM], s1[TDIM];
    float* base = g_P + b * PBSTRIDE;
    s0[tid] = base[tid];
    s0[tid + 256] = base[tid + 256];
    __syncthreads();
    float* cur = s0;
    float* nxt = s1;
    for (int k = 1; k < NLEV; ++k) {
        int h = 1 << (k - 1);
#pragma unroll
        for (int i = 0; i < 2; ++i) {
            int tau = tid + i * 256;
            float v = cur[tau];
            if (tau + h < TDIM) v = fminf(v, cur[tau + h]);
            nxt[tau] = v;
            base[k * TDIM + tau] = v;
        }
        __syncthreads();
        float* tmp = cur; cur = nxt; nxt = tmp;
    }
}

// ---------------- K3: m[t][j] = max_b (c + C_j) ---------------------------
__global__ __launch_bounds__(256) void k_m() {
    int t = blockIdx.x, tid = threadIdx.x;
    __shared__ float sc[BDIM];
    if (tid < BDIM) sc[tid] = g_cTB[t * BDIM + tid];
    __syncthreads();

    for (int tau = tid; tau <= t; tau += 256) {
        int n = t - tau;
        int off1 = 0, off2 = 0;
        if (n) {
            int k = 31 - __clz(n);
            off1 = k * TDIM + tau;
            off2 = k * TDIM + t - (1 << k);
        }
        float me = -INFV, mo = -INFV;
#pragma unroll 4
        for (int b = 0; b < BDIM; ++b) {
            const float* pb = g_P + b * PBSTRIDE;
            float R = n ? fminf(pb[off1], pb[off2]) : INFV;
            float a0 = g_t0T[b * TDIM + tau];
            float p0 = g_TPT[b * TDIM + tau];
            float cb = sc[b];
            me = fmaxf(me, cb + fminf(a0, R));
            mo = fmaxf(mo, cb + fminf(p0, R));
        }
        g_m[(size_t)(2 * tau) * TDIM + t] = me;
        g_m[(size_t)(2 * tau + 1) * TDIM + t] = mo;
    }
}

// ---------------- K4: tiled GEMM with on-the-fly weights ------------------
// CTA: (t-tile of 128) x (batch b). 256 threads, each 8 rows x 8 cols.
__global__ __launch_bounds__(256, 2) void k_gemm(const float* __restrict__ v1,
                                                 const float* __restrict__ v2,
                                                 float* __restrict__ out) {
    int tile = 3 - blockIdx.x;  // heavy tiles first
    int b = blockIdx.y;
    int t0 = tile * 128;
    int tid = threadIdx.x;
    int rg = tid >> 4, cg = tid & 15;
    int r0 = rg * 8, e0 = cg * 8;

    __shared__ float sv1[16][EDIM];
    __shared__ float sv2[16][EDIM];
    __shared__ float swe[16][128];
    __shared__ float swo[16][128];

    unsigned long long acc[8][4];
#pragma unroll
    for (int i = 0; i < 8; ++i)
#pragma unroll
        for (int j = 0; j < 4; ++j) acc[i][j] = 0ull;

    const float* Pb = g_P + b * PBSTRIDE;
    int tw = tid & 127, yw = tid >> 7;
    int tmy = t0 + tw;

    int nstages = (tile + 1) * 8;
    for (int st = 0; st < nstages; ++st) {
        int tauc = st * 16;
        __syncthreads();
        // stage values
        for (int i = tid; i < 16 * EDIM; i += 256) {
            int s = i >> 7, e = i & 127;
            int tau = tauc + s;
            size_t idx = ((size_t)tau * BDIM + b) * EDIM + e;
            sv1[s][e] = v1[idx];
            sv2[s][e] = v2[idx];
        }
        // compute weights W[tau][t]
#pragma unroll
        for (int ti = 0; ti < 8; ++ti) {
            int s = yw * 8 + ti;
            int tau = tauc + s;
            float we = 0.f, wo = 0.f;
            if (tau <= tmy) {
                float a0 = g_t0T[b * TDIM + tau];
                float p0 = g_TPT[b * TDIM + tau];
                int n = tmy - tau;
                float R;
                if (n) {
                    int k = 31 - __clz(n);
                    R = fminf(Pb[k * TDIM + tau], Pb[k * TDIM + tmy - (1 << k)]);
                } else {
                    R = INFV;
                }
                float Ca = fminf(a0, R);
                float Cp = fminf(p0, R);
                float mo = g_m[(size_t)(2 * tau + 1) * TDIM + tmy];
                float me = g_m[(size_t)(2 * tau) * TDIM + tmy];
                wo = fminf(Cp - Ca, mo);
                float Cm1 = 0.f;
                if (tau) {
                    float pm1 = g_TPT[b * TDIM + tau - 1];
                    float lm1 = Pb[tau - 1];
                    Cm1 = fminf(pm1, fminf(lm1, R));
                }
                we = fminf(Ca - Cm1, me);
            }
            swe[s][tw] = we;
            swo[s][tw] = wo;
        }
        __syncthreads();
        // FMA phase (packed f32x2)
#pragma unroll
        for (int s = 0; s < 16; ++s) {
            ulonglong2 vA0 = *(const ulonglong2*)&sv1[s][e0];
            ulonglong2 vA1 = *(const ulonglong2*)&sv1[s][e0 + 4];
            ulonglong2 vB0 = *(const ulonglong2*)&sv2[s][e0];
            ulonglong2 vB1 = *(const ulonglong2*)&sv2[s][e0 + 4];
            unsigned long long va[4] = {vA0.x, vA0.y, vA1.x, vA1.y};
            unsigned long long vb[4] = {vB0.x, vB0.y, vB1.x, vB1.y};
#pragma unroll
            for (int i = 0; i < 8; ++i) {
                unsigned long long wa = pack2(swe[s][r0 + i]);
                unsigned long long wb = pack2(swo[s][r0 + i]);
#pragma unroll
                for (int j = 0; j < 4; ++j) {
                    acc[i][j] = ffma2(wa, va[j], acc[i][j]);
                    acc[i][j] = ffma2(wb, vb[j], acc[i][j]);
                }
            }
        }
    }

    // write out [T][B][E]
#pragma unroll
    for (int i = 0; i < 8; ++i) {
        float r[8];
#pragma unroll
        for (int j = 0; j < 4; ++j) unpack2(acc[i][j], r[2 * j], r[2 * j + 1]);
        size_t basei = ((size_t)(t0 + r0 + i) * BDIM + b) * EDIM + e0;
        *reinterpret_cast<float4*>(out + basei) = make_float4(r[0], r[1], r[2], r[3]);
        *reinterpret_cast<float4*>(out + basei + 4) = make_float4(r[4], r[5], r[6], r[7]);
    }
}

extern "C" void kernel_launch(void* const* d_in, const int* in_sizes, int n_in,
                              void* d_out, int out_size) {
    const float* v1 = (const float*)d_in[0];
    const float* v2 = (const float*)d_in[1];
    const float* d1 = (const float*)d_in[2];
    const float* d2 = (const float*)d_in[3];
    const float* u  = (const float*)d_in[4];
    float* out = (float*)d_out;

    k_lev1<<<8, BDIM>>>(d1, d2, u);
    k_lev2<<<1, BDIM>>>();
    k_lev3<<<8, BDIM>>>(d1, d2, u);
    k_table<<<BDIM, 256>>>();
    k_m<<<TDIM, 256>>>();
    dim3 grid(4, BDIM);
    k_gemm<<<grid, 256>>>(v1, v2, out);
}